// round 14
// baseline (speedup 1.0000x reference)
#include <cuda_runtime.h>
#include <cuda_bf16.h>
#include <cstdint>

#define NN 8192
#define INF_DIM 512
#define OUTF 64
#define ALPHA 0.2f

#define NSLICE 8
#define SLICE_J (NN / NSLICE)     // 1024
#define TI 256                    // i-rows per attn block (8 warps x 2 strips x m16)
#define CJ 64                     // j per chunk
#define NCHUNK (SLICE_J / CJ)     // 16
#define NJT (NN / 16)             // 512 j-tiles (k16)
#define NNT (OUTF / 8)            // 8 n-tiles

typedef unsigned long long ull;

// ---------------- device scratch (no cudaMalloc allowed) -------------------
__device__ float g_h[NN * OUTF];                 // h = X @ W
__device__ float g_fs[NN];                       // s_i
__device__ float g_R[NN];                        // exp(0.8 s_i)
__device__ float4 g_tab[NN];                     // (d_j, exp(d_j), exp(0.2 d_j), 0)
__device__ uint4 g_B[NJT * NNT * 32];            // B frags {hi0,hi1,lo0,lo1} per-lane
__device__ float g_accD[NSLICE * NN * OUTF];     // partial att@h per slice (16MB)
__device__ float g_accZ[NSLICE * NN];            // partial row sums per slice

// ---- helpers --------------------------------------------------------------
__device__ __forceinline__ void ffma2(ull& d, ull a, ull b) {
    asm("fma.rn.f32x2 %0, %1, %2, %0;" : "+l"(d) : "l"(a), "l"(b));
}
__device__ __forceinline__ ull pack2(float x) {
    ull r; unsigned int u = __float_as_uint(x);
    asm("mov.b64 %0, {%1, %1};" : "=l"(r) : "r"(u));
    return r;
}
// pack {lo=b, hi=a} as bf16x2
__device__ __forceinline__ uint32_t bf2(float a, float b) {
    uint32_t r;
    asm("cvt.rn.bf16x2.f32 %0, %1, %2;" : "=r"(r) : "f"(a), "f"(b));
    return r;
}
__device__ __forceinline__ void mma16816(float* c, const uint32_t* a,
                                         uint32_t b0, uint32_t b1) {
    asm volatile(
        "mma.sync.aligned.m16n8k16.row.col.f32.bf16.bf16.f32 "
        "{%0,%1,%2,%3}, {%4,%5,%6,%7}, {%8,%9}, {%0,%1,%2,%3};"
        : "+f"(c[0]), "+f"(c[1]), "+f"(c[2]), "+f"(c[3])
        : "r"(a[0]), "r"(a[1]), "r"(a[2]), "r"(a[3]), "r"(b0), "r"(b1));
}

// ---------------------------------------------------------------------------
// Kernel A: h = X @ W.  Tiled smem GEMM with FFMA2 (verified R4-R12).
// ---------------------------------------------------------------------------
__global__ void __launch_bounds__(256) gemm_h_kernel(const float* __restrict__ X,
                                                     const float* __restrict__ W) {
    __shared__ float w_sh[64 * 64];
    __shared__ float x_sh[64 * 65];

    const int tid = threadIdx.x;
    const int i0 = blockIdx.x * 64;
    const int rg = tid >> 4;
    const int cg = tid & 15;

    ull acc[4][2];
    #pragma unroll
    for (int r = 0; r < 4; ++r) { acc[r][0] = 0ull; acc[r][1] = 0ull; }

    const int xr = tid >> 2;
    const int xk = (tid & 3) * 16;

    for (int kt = 0; kt < INF_DIM; kt += 64) {
        const float4* wsrc = (const float4*)(W + (size_t)kt * OUTF);
        float4* wdst = (float4*)w_sh;
        #pragma unroll
        for (int t = 0; t < 4; ++t) wdst[t * 256 + tid] = wsrc[t * 256 + tid];

        const float4* xsrc = (const float4*)(X + (size_t)(i0 + xr) * INF_DIM + kt + xk);
        #pragma unroll
        for (int t = 0; t < 4; ++t) {
            float4 v = xsrc[t];
            x_sh[(xk + t * 4 + 0) * 65 + xr] = v.x;
            x_sh[(xk + t * 4 + 1) * 65 + xr] = v.y;
            x_sh[(xk + t * 4 + 2) * 65 + xr] = v.z;
            x_sh[(xk + t * 4 + 3) * 65 + xr] = v.w;
        }
        __syncthreads();

        #pragma unroll 4
        for (int k = 0; k < 64; ++k) {
            ull w0 = *(const ull*)(w_sh + k * 64 + cg * 2);
            ull w1 = *(const ull*)(w_sh + k * 64 + cg * 2 + 32);
            const float* xp = x_sh + k * 65 + rg * 4;
            #pragma unroll
            for (int r = 0; r < 4; ++r) {
                ull xx = pack2(xp[r]);
                ffma2(acc[r][0], xx, w0);
                ffma2(acc[r][1], xx, w1);
            }
        }
        __syncthreads();
    }

    #pragma unroll
    for (int r = 0; r < 4; ++r) {
        float* dst = g_h + (size_t)(i0 + rg * 4 + r) * OUTF + cg * 2;
        *(ull*)(dst) = acc[r][0];
        *(ull*)(dst + 32) = acc[r][1];
    }
}

// ---------------------------------------------------------------------------
// Kernel B: f_src/f_dst + factorized exp node terms (verified R5-R12).
//   wgt_ij = adj * ( s_i+d_j >= 0 ? exp(0.8 s_i)*exp(d_j) : exp(0.2 d_j) )
// ---------------------------------------------------------------------------
__global__ void __launch_bounds__(256) fsfd_kernel(const float* __restrict__ a) {
    int lane = threadIdx.x & 31;
    int row = blockIdx.x * 8 + (threadIdx.x >> 5);
    float h0 = g_h[(size_t)row * OUTF + lane];
    float h1 = g_h[(size_t)row * OUTF + lane + 32];
    float fs = h0 * a[lane] + h1 * a[lane + 32];
    float fd = h0 * a[64 + lane] + h1 * a[96 + lane];
    #pragma unroll
    for (int m = 16; m > 0; m >>= 1) {
        fs += __shfl_xor_sync(0xffffffffu, fs, m);
        fd += __shfl_xor_sync(0xffffffffu, fd, m);
    }
    if (lane == 0) {
        g_fs[row] = fs;
        g_R[row] = __expf(0.8f * fs);
        g_tab[row] = make_float4(fd, __expf(fd), __expf(ALPHA * fd), 0.f);
    }
}

// ---------------------------------------------------------------------------
// Kernel B2: precompute B fragments (h as bf16 hi + lo residual), fused uint4.
//   tile (jt, nt), lane l (g=l>>2, q=l&3):
//     hi0 = { h[jt*16+2q][nt*8+g], h[jt*16+2q+1][..] }, hi1 = same at k+8.
// ---------------------------------------------------------------------------
__global__ void __launch_bounds__(256) bfrag_kernel() {
    int idx = blockIdx.x * 256 + threadIdx.x;     // tile*32 + lane
    int lane = idx & 31, tile = idx >> 5;
    int jt = tile >> 3, nt = tile & 7;
    int g = lane >> 2, q = lane & 3;
    int c = nt * 8 + g;
    int j = jt * 16 + 2 * q;

    float v0 = g_h[(size_t)(j + 0) * OUTF + c];
    float v1 = g_h[(size_t)(j + 1) * OUTF + c];
    float v8 = g_h[(size_t)(j + 8) * OUTF + c];
    float v9 = g_h[(size_t)(j + 9) * OUTF + c];

    uint32_t h0 = bf2(v1, v0);
    uint32_t h1 = bf2(v9, v8);
    float r0 = v0 - __uint_as_float(h0 << 16);
    float r1 = v1 - __uint_as_float(h0 & 0xffff0000u);
    float r8 = v8 - __uint_as_float(h1 << 16);
    float r9 = v9 - __uint_as_float(h1 & 0xffff0000u);

    g_B[idx] = make_uint4(h0, h1, bf2(r1, r0), bf2(r9, r8));
}

// ---------------------------------------------------------------------------
// Kernel C: tensor-core attn, 2 strips per warp.  256 threads = 8 warps.
//   Warp w owns strips at rows i0+w*16 and i0+128+w*16 (each m16).
//   Thread computes its own mma A-fragment weights in regs (both strips share
//   the tab values), bf16 hi/lo, 3 mma passes per strip -> each B fragment
//   load (one LDG.128) feeds 6 mmas.  No P smem, no per-chunk barriers.
// ---------------------------------------------------------------------------
__global__ void __launch_bounds__(256, 2) attn_kernel(const int* __restrict__ adj) {
    __shared__ float4 tab_sh[SLICE_J];            // 16KB

    const int tid = threadIdx.x;
    const int w = tid >> 5, lane = tid & 31;
    const int g = lane >> 2, q = lane & 3;
    const int i0 = blockIdx.x * TI;
    const int slice = blockIdx.y;
    const int jbase = slice * SLICE_J;

    #pragma unroll
    for (int t = 0; t < SLICE_J / 256; ++t)
        tab_sh[t * 256 + tid] = g_tab[jbase + t * 256 + tid];
    __syncthreads();

    // strip 0: rows ra0 (g), rb0 (g+8); strip 1: +128
    const int ra0 = i0 + w * 16 + g;
    const int rb0 = ra0 + 8;
    const int ra1 = ra0 + 128;
    const int rb1 = rb0 + 128;
    const float nsa0 = -g_fs[ra0], Ra0 = g_R[ra0];
    const float nsb0 = -g_fs[rb0], Rb0 = g_R[rb0];
    const float nsa1 = -g_fs[ra1], Ra1 = g_R[ra1];
    const float nsb1 = -g_fs[rb1], Rb1 = g_R[rb1];
    const int* adjra0 = adj + (size_t)ra0 * NN + jbase;
    const int* adjrb0 = adj + (size_t)rb0 * NN + jbase;
    const int* adjra1 = adj + (size_t)ra1 * NN + jbase;
    const int* adjrb1 = adj + (size_t)rb1 * NN + jbase;
    float za0 = 0.f, zb0 = 0.f, za1 = 0.f, zb1 = 0.f;

    float acc0[NNT][4], acc1[NNT][4];
    #pragma unroll
    for (int nt = 0; nt < NNT; ++nt)
        #pragma unroll
        for (int t = 0; t < 4; ++t) { acc0[nt][t] = 0.f; acc1[nt][t] = 0.f; }

    for (int ch = 0; ch < NCHUNK; ++ch) {
        #pragma unroll
        for (int kt = 0; kt < 4; ++kt) {
            const int jj = ch * CJ + kt * 16 + 2 * q;

            float4 tA = tab_sh[jj];
            float4 tB = tab_sh[jj + 1];
            float4 tC = tab_sh[jj + 8];
            float4 tD = tab_sh[jj + 9];

            uint32_t ahi0[4], alo0[4], ahi1[4], alo1[4];
            // ---- strip 0 weights ----
            {
                int2 mA = *(const int2*)(adjra0 + jj);
                int2 mC = *(const int2*)(adjra0 + jj + 8);
                int2 nA = *(const int2*)(adjrb0 + jj);
                int2 nC = *(const int2*)(adjrb0 + jj + 8);
                float wAa = (mA.x != 0) ? ((tA.x >= nsa0) ? Ra0 * tA.y : tA.z) : 0.f;
                float wBa = (mA.y != 0) ? ((tB.x >= nsa0) ? Ra0 * tB.y : tB.z) : 0.f;
                float wCa = (mC.x != 0) ? ((tC.x >= nsa0) ? Ra0 * tC.y : tC.z) : 0.f;
                float wDa = (mC.y != 0) ? ((tD.x >= nsa0) ? Ra0 * tD.y : tD.z) : 0.f;
                float wAb = (nA.x != 0) ? ((tA.x >= nsb0) ? Rb0 * tA.y : tA.z) : 0.f;
                float wBb = (nA.y != 0) ? ((tB.x >= nsb0) ? Rb0 * tB.y : tB.z) : 0.f;
                float wCb = (nC.x != 0) ? ((tC.x >= nsb0) ? Rb0 * tC.y : tC.z) : 0.f;
                float wDb = (nC.y != 0) ? ((tD.x >= nsb0) ? Rb0 * tD.y : tD.z) : 0.f;
                za0 += (wAa + wBa) + (wCa + wDa);
                zb0 += (wAb + wBb) + (wCb + wDb);
                ahi0[0] = bf2(wBa, wAa);
                ahi0[1] = bf2(wBb, wAb);
                ahi0[2] = bf2(wDa, wCa);
                ahi0[3] = bf2(wDb, wCb);
                alo0[0] = bf2(wBa - __uint_as_float(ahi0[0] & 0xffff0000u),
                              wAa - __uint_as_float(ahi0[0] << 16));
                alo0[1] = bf2(wBb - __uint_as_float(ahi0[1] & 0xffff0000u),
                              wAb - __uint_as_float(ahi0[1] << 16));
                alo0[2] = bf2(wDa - __uint_as_float(ahi0[2] & 0xffff0000u),
                              wCa - __uint_as_float(ahi0[2] << 16));
                alo0[3] = bf2(wDb - __uint_as_float(ahi0[3] & 0xffff0000u),
                              wCb - __uint_as_float(ahi0[3] << 16));
            }
            // ---- strip 1 weights ----
            {
                int2 mA = *(const int2*)(adjra1 + jj);
                int2 mC = *(const int2*)(adjra1 + jj + 8);
                int2 nA = *(const int2*)(adjrb1 + jj);
                int2 nC = *(const int2*)(adjrb1 + jj + 8);
                float wAa = (mA.x != 0) ? ((tA.x >= nsa1) ? Ra1 * tA.y : tA.z) : 0.f;
                float wBa = (mA.y != 0) ? ((tB.x >= nsa1) ? Ra1 * tB.y : tB.z) : 0.f;
                float wCa = (mC.x != 0) ? ((tC.x >= nsa1) ? Ra1 * tC.y : tC.z) : 0.f;
                float wDa = (mC.y != 0) ? ((tD.x >= nsa1) ? Ra1 * tD.y : tD.z) : 0.f;
                float wAb = (nA.x != 0) ? ((tA.x >= nsb1) ? Rb1 * tA.y : tA.z) : 0.f;
                float wBb = (nA.y != 0) ? ((tB.x >= nsb1) ? Rb1 * tB.y : tB.z) : 0.f;
                float wCb = (nC.x != 0) ? ((tC.x >= nsb1) ? Rb1 * tC.y : tC.z) : 0.f;
                float wDb = (nC.y != 0) ? ((tD.x >= nsb1) ? Rb1 * tD.y : tD.z) : 0.f;
                za1 += (wAa + wBa) + (wCa + wDa);
                zb1 += (wAb + wBb) + (wCb + wDb);
                ahi1[0] = bf2(wBa, wAa);
                ahi1[1] = bf2(wBb, wAb);
                ahi1[2] = bf2(wDa, wCa);
                ahi1[3] = bf2(wDb, wCb);
                alo1[0] = bf2(wBa - __uint_as_float(ahi1[0] & 0xffff0000u),
                              wAa - __uint_as_float(ahi1[0] << 16));
                alo1[1] = bf2(wBb - __uint_as_float(ahi1[1] & 0xffff0000u),
                              wAb - __uint_as_float(ahi1[1] << 16));
                alo1[2] = bf2(wDa - __uint_as_float(ahi1[2] & 0xffff0000u),
                              wCa - __uint_as_float(ahi1[2] << 16));
                alo1[3] = bf2(wDb - __uint_as_float(ahi1[3] & 0xffff0000u),
                              wCb - __uint_as_float(ahi1[3] << 16));
            }

            const size_t tb = ((size_t)((jbase + ch * CJ) >> 4) + kt) * 256 + lane;
            #pragma unroll
            for (int nt = 0; nt < NNT; ++nt) {
                uint4 B = g_B[tb + nt * 32];
                mma16816(acc0[nt], ahi0, B.x, B.y);   // hi*hi
                mma16816(acc0[nt], alo0, B.x, B.y);   // lo*hi
                mma16816(acc0[nt], ahi0, B.z, B.w);   // hi*lo
                mma16816(acc1[nt], ahi1, B.x, B.y);
                mma16816(acc1[nt], alo1, B.x, B.y);
                mma16816(acc1[nt], ahi1, B.z, B.w);
            }
        }
    }

    // ---- epilogue: store D partials + quad-reduced Z ----
    {
        float* da = g_accD + ((size_t)slice * NN + ra0) * OUTF;
        float* db = g_accD + ((size_t)slice * NN + rb0) * OUTF;
        float* dc = g_accD + ((size_t)slice * NN + ra1) * OUTF;
        float* dd = g_accD + ((size_t)slice * NN + rb1) * OUTF;
        #pragma unroll
        for (int nt = 0; nt < NNT; ++nt) {
            *(float2*)(da + nt * 8 + 2 * q) = make_float2(acc0[nt][0], acc0[nt][1]);
            *(float2*)(db + nt * 8 + 2 * q) = make_float2(acc0[nt][2], acc0[nt][3]);
            *(float2*)(dc + nt * 8 + 2 * q) = make_float2(acc1[nt][0], acc1[nt][1]);
            *(float2*)(dd + nt * 8 + 2 * q) = make_float2(acc1[nt][2], acc1[nt][3]);
        }
    }
    za0 += __shfl_xor_sync(0xffffffffu, za0, 1);
    za0 += __shfl_xor_sync(0xffffffffu, za0, 2);
    zb0 += __shfl_xor_sync(0xffffffffu, zb0, 1);
    zb0 += __shfl_xor_sync(0xffffffffu, zb0, 2);
    za1 += __shfl_xor_sync(0xffffffffu, za1, 1);
    za1 += __shfl_xor_sync(0xffffffffu, za1, 2);
    zb1 += __shfl_xor_sync(0xffffffffu, zb1, 1);
    zb1 += __shfl_xor_sync(0xffffffffu, zb1, 2);
    if (q == 0) {
        g_accZ[(size_t)slice * NN + ra0] = za0;
        g_accZ[(size_t)slice * NN + rb0] = zb0;
        g_accZ[(size_t)slice * NN + ra1] = za1;
        g_accZ[(size_t)slice * NN + rb1] = zb1;
    }
}

// ---------------------------------------------------------------------------
// Kernel D: combine slices, normalize, ELU, store.
// ---------------------------------------------------------------------------
__global__ void __launch_bounds__(256) combine_kernel(float* __restrict__ out) {
    int idx = blockIdx.x * 256 + threadIdx.x;
    int i = idx >> 6;
    float s = 0.f, z = 0.f;
    #pragma unroll
    for (int k = 0; k < NSLICE; ++k) {
        s += g_accD[(size_t)k * NN * OUTF + idx];
        z += g_accZ[(size_t)k * NN + i];
    }
    float v = s / z;
    v = (v > 0.f) ? v : expm1f(v);
    out[idx] = v;
}

// ---------------------------------------------------------------------------
extern "C" void kernel_launch(void* const* d_in, const int* in_sizes, int n_in,
                              void* d_out, int out_size) {
    const float* X = (const float*)d_in[0];   // [8192, 512] f32
    const int* adj = (const int*)d_in[1];     // [8192, 8192] i32
    const float* W = (const float*)d_in[2];   // [512, 64] f32
    const float* a = (const float*)d_in[3];   // [128, 1] f32
    float* out = (float*)d_out;               // [8192, 64] f32

    gemm_h_kernel<<<NN / 64, 256>>>(X, W);
    fsfd_kernel<<<NN / 8, 256>>>(a);
    bfrag_kernel<<<NJT * NNT * 32 / 256, 256>>>();
    attn_kernel<<<dim3(NN / TI, NSLICE), 256>>>(adj);
    combine_kernel<<<NN * OUTF / 256, 256>>>(out);
}

// round 15
// speedup vs baseline: 1.6846x; 1.6846x over previous
#include <cuda_runtime.h>
#include <cuda_bf16.h>
#include <cstdint>

#define NN 8192
#define INF_DIM 512
#define OUTF 64
#define ALPHA 0.2f

#define NSLICE 4
#define SLICE_J (NN / NSLICE)     // 2048
#define TI 128                    // i-rows per attn block (8 warps x m16)
#define CJ 64                     // j per chunk
#define NCHUNK (SLICE_J / CJ)     // 32
#define NJT (NN / 16)             // 512 j-tiles (k16)
#define NNT (OUTF / 8)            // 8 n-tiles

typedef unsigned long long ull;

// ---------------- device scratch (no cudaMalloc allowed) -------------------
__device__ float g_h[NN * OUTF];                 // h = X @ W
__device__ float g_fs[NN];                       // s_i
__device__ float g_R[NN];                        // exp(0.8 s_i)
__device__ float4 g_tab[NN];                     // (d_j, exp(d_j), exp(0.2 d_j), 0)
__device__ uint4 g_B[NJT * NNT * 32];            // B frags {hi0,hi1,lo0,lo1} per-lane
__device__ float g_accD[NSLICE * NN * OUTF];     // partial att@h per slice
__device__ float g_accZ[NSLICE * NN];            // partial row sums per slice

// ---- helpers --------------------------------------------------------------
__device__ __forceinline__ void ffma2(ull& d, ull a, ull b) {
    asm("fma.rn.f32x2 %0, %1, %2, %0;" : "+l"(d) : "l"(a), "l"(b));
}
__device__ __forceinline__ ull pack2(float x) {
    ull r; unsigned int u = __float_as_uint(x);
    asm("mov.b64 %0, {%1, %1};" : "=l"(r) : "r"(u));
    return r;
}
// pack {lo=b, hi=a} as bf16x2
__device__ __forceinline__ uint32_t bf2(float a, float b) {
    uint32_t r;
    asm("cvt.rn.bf16x2.f32 %0, %1, %2;" : "=r"(r) : "f"(a), "f"(b));
    return r;
}
__device__ __forceinline__ void mma16816(float* c, const uint32_t* a,
                                         uint32_t b0, uint32_t b1) {
    asm volatile(
        "mma.sync.aligned.m16n8k16.row.col.f32.bf16.bf16.f32 "
        "{%0,%1,%2,%3}, {%4,%5,%6,%7}, {%8,%9}, {%0,%1,%2,%3};"
        : "+f"(c[0]), "+f"(c[1]), "+f"(c[2]), "+f"(c[3])
        : "r"(a[0]), "r"(a[1]), "r"(a[2]), "r"(a[3]), "r"(b0), "r"(b1));
}

// ---------------------------------------------------------------------------
// Kernel A: h = X @ W.  Tiled smem GEMM with FFMA2 (verified R4-R12).
// ---------------------------------------------------------------------------
__global__ void __launch_bounds__(256) gemm_h_kernel(const float* __restrict__ X,
                                                     const float* __restrict__ W) {
    __shared__ float w_sh[64 * 64];
    __shared__ float x_sh[64 * 65];

    const int tid = threadIdx.x;
    const int i0 = blockIdx.x * 64;
    const int rg = tid >> 4;
    const int cg = tid & 15;

    ull acc[4][2];
    #pragma unroll
    for (int r = 0; r < 4; ++r) { acc[r][0] = 0ull; acc[r][1] = 0ull; }

    const int xr = tid >> 2;
    const int xk = (tid & 3) * 16;

    for (int kt = 0; kt < INF_DIM; kt += 64) {
        const float4* wsrc = (const float4*)(W + (size_t)kt * OUTF);
        float4* wdst = (float4*)w_sh;
        #pragma unroll
        for (int t = 0; t < 4; ++t) wdst[t * 256 + tid] = wsrc[t * 256 + tid];

        const float4* xsrc = (const float4*)(X + (size_t)(i0 + xr) * INF_DIM + kt + xk);
        #pragma unroll
        for (int t = 0; t < 4; ++t) {
            float4 v = xsrc[t];
            x_sh[(xk + t * 4 + 0) * 65 + xr] = v.x;
            x_sh[(xk + t * 4 + 1) * 65 + xr] = v.y;
            x_sh[(xk + t * 4 + 2) * 65 + xr] = v.z;
            x_sh[(xk + t * 4 + 3) * 65 + xr] = v.w;
        }
        __syncthreads();

        #pragma unroll 4
        for (int k = 0; k < 64; ++k) {
            ull w0 = *(const ull*)(w_sh + k * 64 + cg * 2);
            ull w1 = *(const ull*)(w_sh + k * 64 + cg * 2 + 32);
            const float* xp = x_sh + k * 65 + rg * 4;
            #pragma unroll
            for (int r = 0; r < 4; ++r) {
                ull xx = pack2(xp[r]);
                ffma2(acc[r][0], xx, w0);
                ffma2(acc[r][1], xx, w1);
            }
        }
        __syncthreads();
    }

    #pragma unroll
    for (int r = 0; r < 4; ++r) {
        float* dst = g_h + (size_t)(i0 + rg * 4 + r) * OUTF + cg * 2;
        *(ull*)(dst) = acc[r][0];
        *(ull*)(dst + 32) = acc[r][1];
    }
}

// ---------------------------------------------------------------------------
// Kernel B: f_src/f_dst + factorized exp node terms (verified R5-R12).
//   wgt_ij = adj * ( s_i+d_j >= 0 ? exp(0.8 s_i)*exp(d_j) : exp(0.2 d_j) )
// ---------------------------------------------------------------------------
__global__ void __launch_bounds__(256) fsfd_kernel(const float* __restrict__ a) {
    int lane = threadIdx.x & 31;
    int row = blockIdx.x * 8 + (threadIdx.x >> 5);
    float h0 = g_h[(size_t)row * OUTF + lane];
    float h1 = g_h[(size_t)row * OUTF + lane + 32];
    float fs = h0 * a[lane] + h1 * a[lane + 32];
    float fd = h0 * a[64 + lane] + h1 * a[96 + lane];
    #pragma unroll
    for (int m = 16; m > 0; m >>= 1) {
        fs += __shfl_xor_sync(0xffffffffu, fs, m);
        fd += __shfl_xor_sync(0xffffffffu, fd, m);
    }
    if (lane == 0) {
        g_fs[row] = fs;
        g_R[row] = __expf(0.8f * fs);
        g_tab[row] = make_float4(fd, __expf(fd), __expf(ALPHA * fd), 0.f);
    }
}

// ---------------------------------------------------------------------------
// Kernel B2: precompute B fragments with the PERMUTED k<->j mapping.
//   Within each k16 tile, thread q's mma k-indices {2q,2q+1,2q+8,2q+9}
//   are fed by CONTIGUOUS j = {4q, 4q+1, 4q+2, 4q+3}.  (j is a reduction
//   axis; any permutation is legal as long as A and B agree.)
//   tile (jt, nt), lane l (g=l>>2, q=l&3), c = nt*8+g, j = jt*16+4q:
//     hi0 = {h[j], h[j+1]},  hi1 = {h[j+2], h[j+3]}  (bf16 hi)
//     lo0, lo1 = bf16 of residuals.
// ---------------------------------------------------------------------------
__global__ void __launch_bounds__(256) bfrag_kernel() {
    int idx = blockIdx.x * 256 + threadIdx.x;     // tile*32 + lane
    int lane = idx & 31, tile = idx >> 5;
    int jt = tile >> 3, nt = tile & 7;
    int g = lane >> 2, q = lane & 3;
    int c = nt * 8 + g;
    int j = jt * 16 + 4 * q;

    float v0 = g_h[(size_t)(j + 0) * OUTF + c];
    float v1 = g_h[(size_t)(j + 1) * OUTF + c];
    float v2 = g_h[(size_t)(j + 2) * OUTF + c];
    float v3 = g_h[(size_t)(j + 3) * OUTF + c];

    uint32_t h0 = bf2(v1, v0);
    uint32_t h1 = bf2(v3, v2);
    float r0 = v0 - __uint_as_float(h0 << 16);
    float r1 = v1 - __uint_as_float(h0 & 0xffff0000u);
    float r2 = v2 - __uint_as_float(h1 << 16);
    float r3 = v3 - __uint_as_float(h1 & 0xffff0000u);

    g_B[idx] = make_uint4(h0, h1, bf2(r1, r0), bf2(r3, r2));
}

// ---------------------------------------------------------------------------
// Kernel C: tensor-core attn (R12 structure + permuted mapping).
//   256 threads = 8 warps, warp w = rows i0+w*16 .. +15 (one m16 strip).
//   Per kt, thread (g,q) loads ONE aligned int4 of adj per row (j=4q..4q+3)
//   instead of two scattered int2s -> adj L1 wavefronts halved.
//   Weights -> bf16 hi/lo -> 3-pass m16n8k16 (hi*hi + lo*hi + hi*lo).
//   Z per-thread fp32 + quad shfl.  No P smem, no per-chunk barriers.
// ---------------------------------------------------------------------------
__global__ void __launch_bounds__(256, 2) attn_kernel(const int* __restrict__ adj) {
    __shared__ float4 tab_sh[SLICE_J];            // 32KB

    const int tid = threadIdx.x;
    const int w = tid >> 5, lane = tid & 31;
    const int g = lane >> 2, q = lane & 3;
    const int i0 = blockIdx.x * TI;
    const int slice = blockIdx.y;
    const int jbase = slice * SLICE_J;

    #pragma unroll
    for (int t = 0; t < SLICE_J / 256; ++t)
        tab_sh[t * 256 + tid] = g_tab[jbase + t * 256 + tid];
    __syncthreads();

    const int ra = i0 + w * 16 + g;
    const int rb = ra + 8;
    const float nsa = -g_fs[ra], Ra = g_R[ra];
    const float nsb = -g_fs[rb], Rb = g_R[rb];
    const int* adjra = adj + (size_t)ra * NN + jbase;
    const int* adjrb = adj + (size_t)rb * NN + jbase;
    float za = 0.f, zb = 0.f;

    float acc[NNT][4];
    #pragma unroll
    for (int nt = 0; nt < NNT; ++nt)
        #pragma unroll
        for (int t = 0; t < 4; ++t) acc[nt][t] = 0.f;

    for (int ch = 0; ch < NCHUNK; ++ch) {
        #pragma unroll
        for (int kt = 0; kt < 4; ++kt) {
            const int jj = ch * CJ + kt * 16 + 4 * q;   // contiguous 4-j group

            float4 t0 = tab_sh[jj];
            float4 t1 = tab_sh[jj + 1];
            float4 t2 = tab_sh[jj + 2];
            float4 t3 = tab_sh[jj + 3];
            int4 ma = __ldcs((const int4*)(adjra + jj));
            int4 mb = __ldcs((const int4*)(adjrb + jj));

            // weights: w_d feeds k = 2q+d (d=0,1) and k = 2q+8+d (d=2,3)
            float wa0 = (ma.x != 0) ? ((t0.x >= nsa) ? Ra * t0.y : t0.z) : 0.f;
            float wa1 = (ma.y != 0) ? ((t1.x >= nsa) ? Ra * t1.y : t1.z) : 0.f;
            float wa2 = (ma.z != 0) ? ((t2.x >= nsa) ? Ra * t2.y : t2.z) : 0.f;
            float wa3 = (ma.w != 0) ? ((t3.x >= nsa) ? Ra * t3.y : t3.z) : 0.f;
            float wb0 = (mb.x != 0) ? ((t0.x >= nsb) ? Rb * t0.y : t0.z) : 0.f;
            float wb1 = (mb.y != 0) ? ((t1.x >= nsb) ? Rb * t1.y : t1.z) : 0.f;
            float wb2 = (mb.z != 0) ? ((t2.x >= nsb) ? Rb * t2.y : t2.z) : 0.f;
            float wb3 = (mb.w != 0) ? ((t3.x >= nsb) ? Rb * t3.y : t3.z) : 0.f;

            za += (wa0 + wa1) + (wa2 + wa3);
            zb += (wb0 + wb1) + (wb2 + wb3);

            uint32_t ahi[4], alo[4];
            ahi[0] = bf2(wa1, wa0);      // row g,   k-lo
            ahi[1] = bf2(wb1, wb0);      // row g+8, k-lo
            ahi[2] = bf2(wa3, wa2);      // row g,   k-hi
            ahi[3] = bf2(wb3, wb2);      // row g+8, k-hi
            alo[0] = bf2(wa1 - __uint_as_float(ahi[0] & 0xffff0000u),
                         wa0 - __uint_as_float(ahi[0] << 16));
            alo[1] = bf2(wb1 - __uint_as_float(ahi[1] & 0xffff0000u),
                         wb0 - __uint_as_float(ahi[1] << 16));
            alo[2] = bf2(wa3 - __uint_as_float(ahi[2] & 0xffff0000u),
                         wa2 - __uint_as_float(ahi[2] << 16));
            alo[3] = bf2(wb3 - __uint_as_float(ahi[3] & 0xffff0000u),
                         wb2 - __uint_as_float(ahi[3] << 16));

            const size_t tb = ((size_t)((jbase + ch * CJ) >> 4) + kt) * 256 + lane;
            #pragma unroll
            for (int nt = 0; nt < NNT; ++nt) {
                uint4 B = g_B[tb + nt * 32];
                mma16816(acc[nt], ahi, B.x, B.y);   // hi*hi
                mma16816(acc[nt], alo, B.x, B.y);   // lo*hi
                mma16816(acc[nt], ahi, B.z, B.w);   // hi*lo
            }
        }
    }

    // ---- epilogue: store D partials + quad-reduced Z ----
    float* da = g_accD + ((size_t)slice * NN + ra) * OUTF;
    float* db = g_accD + ((size_t)slice * NN + rb) * OUTF;
    #pragma unroll
    for (int nt = 0; nt < NNT; ++nt) {
        *(float2*)(da + nt * 8 + 2 * q) = make_float2(acc[nt][0], acc[nt][1]);
        *(float2*)(db + nt * 8 + 2 * q) = make_float2(acc[nt][2], acc[nt][3]);
    }
    za += __shfl_xor_sync(0xffffffffu, za, 1);
    za += __shfl_xor_sync(0xffffffffu, za, 2);
    zb += __shfl_xor_sync(0xffffffffu, zb, 1);
    zb += __shfl_xor_sync(0xffffffffu, zb, 2);
    if (q == 0) {
        g_accZ[(size_t)slice * NN + ra] = za;
        g_accZ[(size_t)slice * NN + rb] = zb;
    }
}

// ---------------------------------------------------------------------------
// Kernel D: combine slices, normalize, ELU, store.
// ---------------------------------------------------------------------------
__global__ void __launch_bounds__(256) combine_kernel(float* __restrict__ out) {
    int idx = blockIdx.x * 256 + threadIdx.x;
    int i = idx >> 6;
    float s = 0.f, z = 0.f;
    #pragma unroll
    for (int k = 0; k < NSLICE; ++k) {
        s += g_accD[(size_t)k * NN * OUTF + idx];
        z += g_accZ[(size_t)k * NN + i];
    }
    float v = s / z;
    v = (v > 0.f) ? v : expm1f(v);
    out[idx] = v;
}

// ---------------------------------------------------------------------------
extern "C" void kernel_launch(void* const* d_in, const int* in_sizes, int n_in,
                              void* d_out, int out_size) {
    const float* X = (const float*)d_in[0];   // [8192, 512] f32
    const int* adj = (const int*)d_in[1];     // [8192, 8192] i32
    const float* W = (const float*)d_in[2];   // [512, 64] f32
    const float* a = (const float*)d_in[3];   // [128, 1] f32
    float* out = (float*)d_out;               // [8192, 64] f32

    gemm_h_kernel<<<NN / 64, 256>>>(X, W);
    fsfd_kernel<<<NN / 8, 256>>>(a);
    bfrag_kernel<<<NJT * NNT * 32 / 256, 256>>>();
    attn_kernel<<<dim3(NN / TI, NSLICE), 256>>>(adj);
    combine_kernel<<<NN * OUTF / 256, 256>>>(out);
}